// round 2
// baseline (speedup 1.0000x reference)
#include <cuda_runtime.h>

#define NV 100000
#define NE 1600000
#define ZD 192
#define HD 512
#define OD 64
#define EPS 1e-5f

typedef unsigned long long ull;

__device__ __forceinline__ ull pack2(float lo, float hi){
    ull r; asm("mov.b64 %0, {%1,%2};" : "=l"(r) : "f"(lo), "f"(hi)); return r;
}
__device__ __forceinline__ void fma2(ull &d, ull a, ull b){
    asm("fma.rn.f32x2 %0, %1, %2, %0;" : "+l"(d) : "l"(a), "l"(b));
}
__device__ __forceinline__ float2 unpack2(ull v){
    float2 f; asm("mov.b64 {%0,%1}, %2;" : "=f"(f.x), "=f"(f.y) : "l"(v)); return f;
}

// scratch (no allocations allowed)
__device__ int   g_deg[NV];
__device__ int   g_off[NV];
__device__ int   g_cur[NV];
__device__ int   g_csc[NE];
__device__ float g_norm[NV];
__device__ float g_tA[NV*64];
__device__ float g_tB[NV*64];
__device__ float g_H[(size_t)NV*ZD];   // [h1|h2|h3] per node
__device__ float g_S[ZD*ZD];           // Gram
__device__ float g_cs[ZD];             // column sums
__device__ float g_M[HD*ZD];           // folded weights
__device__ float g_cv[HD];             // folded bias
__device__ float g_av[HD];             // q*gamma*invstd
__device__ float g_dt[HD];             // per-channel const
__device__ float g_V[ZD*OD];
__device__ float g_dc[OD];
__device__ int   g_bsum[128];
__device__ int   g_boff[128];

__global__ void k_zero(){
    int i = blockIdx.x*256 + threadIdx.x;
    if (i < NV)    g_deg[i] = 0;
    if (i < ZD*ZD) g_S[i]   = 0.f;
    if (i < ZD)    g_cs[i]  = 0.f;
}

// M_j = fc_W_j @ W_j ; c = fc_W @ [b0;b1;b2] + fc_b
__global__ void k_weights(const float* __restrict__ fcW,
                          const float* __restrict__ W0, const float* __restrict__ W1,
                          const float* __restrict__ W2,
                          const float* __restrict__ b0, const float* __restrict__ b1,
                          const float* __restrict__ b2, const float* __restrict__ fcb){
    int idx = blockIdx.x*256 + threadIdx.x;
    if (idx < HD*ZD){
        int ko = idx / ZD, i = idx - ko*ZD;
        int j = i >> 6, d = i & 63;
        const float* W  = (j==0)?W0:((j==1)?W1:W2);
        const float* fr = fcW + ko*1536 + j*512;
        float s = 0.f;
        #pragma unroll 4
        for (int h=0; h<HD; h++) s = fmaf(fr[h], W[h*64+d], s);
        g_M[ko*ZD+i] = s;
    } else if (idx < HD*ZD + HD){
        int ko = idx - HD*ZD;
        const float* fr = fcW + ko*1536;
        float s = fcb[ko];
        for (int h=0; h<HD; h++)
            s += fr[h]*b0[h] + fr[512+h]*b1[h] + fr[1024+h]*b2[h];
        g_cv[ko] = s;
    }
}

__global__ void k_deg(const int* __restrict__ dst){
    int e = blockIdx.x*256 + threadIdx.x;
    if (e < NE) atomicAdd(&g_deg[dst[e]], 1);
}

__global__ void k_scan1(){
    __shared__ int sh[1024];
    int t = threadIdx.x, i = blockIdx.x*1024 + t;
    int v = (i < NV) ? g_deg[i] : 0;
    sh[t] = v; __syncthreads();
    for (int off=1; off<1024; off<<=1){
        int x = (t >= off) ? sh[t-off] : 0; __syncthreads();
        sh[t] += x; __syncthreads();
    }
    if (i < NV) g_off[i] = sh[t] - v;
    if (t == 1023) g_bsum[blockIdx.x] = sh[1023];
}

__global__ void k_scan2(){
    __shared__ int sh[128];
    int t = threadIdx.x;
    int v = (t < 98) ? g_bsum[t] : 0;
    sh[t] = v; __syncthreads();
    for (int off=1; off<128; off<<=1){
        int x = (t >= off) ? sh[t-off] : 0; __syncthreads();
        sh[t] += x; __syncthreads();
    }
    g_boff[t] = sh[t] - v;
}

__global__ void k_scan3(){
    int i = blockIdx.x*256 + threadIdx.x;
    if (i < NV){
        int o = g_off[i] + g_boff[i >> 10];
        g_off[i] = o; g_cur[i] = o;
        int d = g_deg[i];
        g_norm[i] = rsqrtf((float)(d > 1 ? d : 1));
    }
}

__global__ void k_place(const int* __restrict__ src, const int* __restrict__ dst){
    int e = blockIdx.x*256 + threadIdx.x;
    if (e < NE){
        int p = atomicAdd(&g_cur[dst[e]], 1);
        g_csc[p] = src[e];
    }
}

__global__ void k_t0(const float* __restrict__ feats){
    int i = blockIdx.x*256 + threadIdx.x;
    if (i < NV*64) g_tA[i] = feats[i] * g_norm[i >> 6];
}

// one hop: h[v] = norm[v] * sum_{u in N(v)} t[u]; next t = h*norm
__global__ void k_hop(int sel, int coff){
    int gw   = (blockIdx.x*blockDim.x + threadIdx.x) >> 5;
    int lane = threadIdx.x & 31;
    if (gw >= NV) return;
    const float2* tin  = (const float2*)(sel ? g_tB : g_tA);
    float2*       tout = (float2*)(sel ? g_tA : g_tB);
    int s = g_off[gw], e = s + g_deg[gw];
    float ax = 0.f, ay = 0.f;
    int i = s;
    for (; i + 1 < e; i += 2){
        int u0 = g_csc[i], u1 = g_csc[i+1];
        float2 a = __ldg(&tin[u0*32 + lane]);
        float2 b = __ldg(&tin[u1*32 + lane]);
        ax += a.x + b.x; ay += a.y + b.y;
    }
    if (i < e){
        int u = g_csc[i];
        float2 a = __ldg(&tin[u*32 + lane]);
        ax += a.x; ay += a.y;
    }
    float nv = g_norm[gw];
    float hx = ax*nv, hy = ay*nv;
    ((float2*)(g_H + (size_t)gw*ZD + coff))[lane] = make_float2(hx, hy);
    tout[gw*32 + lane] = make_float2(hx*nv, hy*nv);
}

// Gram: persistent blocks, 16x16 threads, 12x12 reg tiles, f32x2
__global__ void __launch_bounds__(256,1) k_gram(){
    __shared__ float zs[64*ZD];        // 48KB
    int tid = threadIdx.x, ti = tid & 15, tj = tid >> 4;
    ull acc[12][6];
    #pragma unroll
    for (int a=0;a<12;a++){
        #pragma unroll
        for (int b=0;b<6;b++) acc[a][b] = 0ULL;
    }
    float csum[12];
    #pragma unroll
    for (int a=0;a<12;a++) csum[a] = 0.f;

    int ntile = (NV + 63) >> 6;
    for (int tile = blockIdx.x; tile < ntile; tile += gridDim.x){
        int r0 = tile << 6;
        int valid = NV - r0; if (valid > 64) valid = 64;
        for (int t = tid; t < 64*ZD/4; t += 256){
            int r = t / (ZD/4);
            float4 v = (r < valid) ? __ldg(((const float4*)(g_H + (size_t)r0*ZD)) + t)
                                   : make_float4(0.f,0.f,0.f,0.f);
            ((float4*)zs)[t] = v;
        }
        __syncthreads();
        for (int r=0; r<64; r++){
            const float* row = zs + r*ZD;
            ull zj[6];
            #pragma unroll
            for (int b=0;b<6;b++) zj[b] = ((const ull*)row)[tj*6 + b];
            #pragma unroll
            for (int a=0;a<12;a++){
                float z = row[ti*12 + a];
                if (tj == 0) csum[a] += z;
                ull zz = pack2(z, z);
                #pragma unroll
                for (int b=0;b<6;b++) fma2(acc[a][b], zz, zj[b]);
            }
        }
        __syncthreads();
    }
    #pragma unroll
    for (int a=0;a<12;a++){
        int i = ti*12 + a;
        #pragma unroll
        for (int b=0;b<6;b++){
            float2 p = unpack2(acc[a][b]);
            atomicAdd(&g_S[i*ZD + tj*12 + 2*b],     p.x);
            atomicAdd(&g_S[i*ZD + tj*12 + 2*b + 1], p.y);
        }
    }
    if (tj == 0){
        #pragma unroll
        for (int a=0;a<12;a++) atomicAdd(&g_cs[ti*12 + a], csum[a]);
    }
}

// BN stats per output channel; fold with q
__global__ void k_stats(const float* __restrict__ gamma, const float* __restrict__ beta,
                        const float* __restrict__ q){
    __shared__ float m[ZD], r1[ZD], r2[ZD];
    int ko = blockIdx.x, t = threadIdx.x;
    m[t] = g_M[ko*ZD + t];
    __syncthreads();
    float w = 0.f;
    const float* Srow = g_S + t*ZD;
    #pragma unroll 4
    for (int j=0;j<ZD;j++) w = fmaf(Srow[j], m[j], w);
    r1[t] = m[t]*w;
    r2[t] = m[t]*g_cs[t];
    __syncthreads();
    for (int s=96; s>=3; s>>=1){
        if (t < s){ r1[t] += r1[t+s]; r2[t] += r2[t+s]; }
        __syncthreads();
    }
    if (t == 0){
        float qf  = r1[0]+r1[1]+r1[2];
        float mz  = (r2[0]+r2[1]+r2[2]) * (1.0f/NV);
        float var = qf*(1.0f/NV) - mz*mz;
        float c   = g_cv[ko];
        float inv = rsqrtf(var + EPS);
        float sc  = gamma[ko]*inv;
        float tsh = beta[ko] - (mz + c)*sc;
        float qk  = q[ko >> 6];
        g_av[ko] = qk*sc;
        g_dt[ko] = qk*(sc*c + tsh);
    }
}

__global__ void k_vk(){
    int idx = blockIdx.x*256 + threadIdx.x;
    if (idx < ZD*OD){
        int i = idx >> 6, o = idx & 63;
        float s = 0.f;
        #pragma unroll
        for (int k=0;k<8;k++){ int ko = k*64+o; s = fmaf(g_av[ko], g_M[ko*ZD + i], s); }
        g_V[idx] = s;
    } else if (idx < ZD*OD + OD){
        int o = idx - ZD*OD;
        float s = 0.f;
        #pragma unroll
        for (int k=0;k<8;k++) s += g_dt[k*64+o];
        g_dc[o] = s;
    }
}

// out = H @ V^T + dconst ; 128 rows/block, thread = 4 rows x 8 cols
__global__ void __launch_bounds__(256) k_out(float* __restrict__ out){
    __shared__ float Vs[32*64];        // V chunk [32k][64o]
    __shared__ float zs[128*33];       // H chunk, padded
    int tid = threadIdx.x;
    int tc = tid & 7, tr = tid >> 3;   // cols tc*8.., rows tr*4..
    int r0 = blockIdx.x * 128;
    int valid = NV - r0; if (valid > 128) valid = 128;

    ull acc[4][4];
    #pragma unroll
    for (int a=0;a<4;a++){
        #pragma unroll
        for (int b=0;b<4;b++) acc[a][b] = 0ULL;
    }

    for (int kk=0; kk<ZD; kk+=32){
        for (int t = tid; t < 512; t += 256)
            ((float4*)Vs)[t] = __ldg(((const float4*)(g_V + kk*64)) + t);
        for (int t = tid; t < 1024; t += 256){
            int r = t >> 3, c = t & 7;
            float4 v = (r < valid)
                ? __ldg((const float4*)(g_H + (size_t)(r0+r)*ZD + kk) + c)
                : make_float4(0.f,0.f,0.f,0.f);
            float* d = zs + r*33 + c*4;
            d[0]=v.x; d[1]=v.y; d[2]=v.z; d[3]=v.w;
        }
        __syncthreads();
        #pragma unroll 4
        for (int k=0;k<32;k++){
            ull vv[4];
            #pragma unroll
            for (int c=0;c<4;c++) vv[c] = ((const ull*)(Vs + k*64))[tc*4 + c];
            #pragma unroll
            for (int rr=0;rr<4;rr++){
                float z = zs[(tr*4+rr)*33 + k];
                ull zz = pack2(z, z);
                #pragma unroll
                for (int c=0;c<4;c++) fma2(acc[rr][c], zz, vv[c]);
            }
        }
        __syncthreads();
    }
    #pragma unroll
    for (int rr=0;rr<4;rr++){
        int row = r0 + tr*4 + rr;
        if (row < NV){
            float2* o2 = (float2*)(out + (size_t)row*64 + tc*8);
            #pragma unroll
            for (int c=0;c<4;c++){
                float2 p = unpack2(acc[rr][c]);
                p.x += g_dc[tc*8 + 2*c];
                p.y += g_dc[tc*8 + 2*c + 1];
                o2[c] = p;
            }
        }
    }
}

extern "C" void kernel_launch(void* const* d_in, const int* in_sizes, int n_in,
                              void* d_out, int out_size){
    const float* feats = (const float*)d_in[0];
    const int*   src   = (const int*)  d_in[1];
    const int*   dst   = (const int*)  d_in[2];
    const float* W0    = (const float*)d_in[3];
    const float* b0    = (const float*)d_in[4];
    const float* W1    = (const float*)d_in[5];
    const float* b1    = (const float*)d_in[6];
    const float* W2    = (const float*)d_in[7];
    const float* b2    = (const float*)d_in[8];
    const float* fcW   = (const float*)d_in[9];
    const float* fcb   = (const float*)d_in[10];
    const float* gamma = (const float*)d_in[11];
    const float* beta  = (const float*)d_in[12];
    const float* q     = (const float*)d_in[13];
    float* out = (float*)d_out;

    k_zero   <<<391, 256>>>();
    k_weights<<<387, 256>>>(fcW, W0, W1, W2, b0, b1, b2, fcb);
    k_deg    <<<6250, 256>>>(dst);
    k_scan1  <<<98, 1024>>>();
    k_scan2  <<<1, 128>>>();
    k_scan3  <<<391, 256>>>();
    k_place  <<<6250, 256>>>(src, dst);
    k_t0     <<<25000, 256>>>(feats);
    k_hop    <<<12500, 256>>>(0, 0);
    k_hop    <<<12500, 256>>>(1, 64);
    k_hop    <<<12500, 256>>>(0, 128);
    k_gram   <<<148, 256>>>();
    k_stats  <<<512, 192>>>(gamma, beta, q);
    k_vk     <<<49, 256>>>();
    k_out    <<<782, 256>>>(out);
}